// round 3
// baseline (speedup 1.0000x reference)
#include <cuda_runtime.h>
#include <cstdint>

// ============================================================================
// out[m,b,o] = relu( sum_i inp[m,b,i] * w[m,i,o] + bias[m,o] )
// M=8, B=4096, D_IN=512, D_OUT=512, fp32.
//
// compute_100 (family-portable) path: mma.sync.aligned.m16n8k8 tf32 GEMM.
// CTA tile 128x128, 8 warps (2x4) of 64x32 warp tiles, K-chunks of 32,
// 3-stage cp.async pipeline, fused bias+relu epilogue.
// No tcgen05 (rejected by ptxas at virtual arch compute_100).
// ============================================================================

static constexpr int MDIM = 8;
static constexpr int BDIM = 4096;
static constexpr int DIN  = 512;
static constexpr int DOUT = 512;

static constexpr int BM = 128;
static constexpr int BN = 128;
static constexpr int KC = 32;              // K per pipeline chunk
static constexpr int NCHUNK = DIN / KC;    // 16
static constexpr int NSTAGE = 3;
static constexpr int THREADS = 256;

// Padded SMEM strides (floats). Both are multiples of 4 floats (16B) so
// cp.async 16B stores stay aligned.
static constexpr int ASTR = 36;            // A row stride: 32 data + 4 pad
static constexpr int BSTR = 132;           // B row stride: 128 data + 4 pad
static constexpr int A_BYTES = BM * ASTR * 4;   // 18432
static constexpr int B_BYTES = KC * BSTR * 4;   // 16896
static constexpr int STAGE_BYTES = A_BYTES + B_BYTES;     // 35328
static constexpr int SMEM_TOTAL  = NSTAGE * STAGE_BYTES;  // 105984

__device__ __forceinline__ uint32_t smem_u32(const void* p) {
    uint32_t a;
    asm("{ .reg .u64 t; cvta.to.shared.u64 t, %1; cvt.u32.u64 %0, t; }"
        : "=r"(a) : "l"(p));
    return a;
}

__device__ __forceinline__ void cp16(uint32_t dst, const void* src) {
    asm volatile("cp.async.cg.shared.global [%0], [%1], 16;"
                 :: "r"(dst), "l"(src) : "memory");
}

__device__ __forceinline__ uint32_t to_tf32(float f) {
    uint32_t u;
    asm("cvt.rna.tf32.f32 %0, %1;" : "=r"(u) : "f"(f));
    return u;
}

__device__ __forceinline__ void mma_tf32(float* c, const uint32_t* a,
                                         const uint32_t* b) {
    asm volatile(
        "mma.sync.aligned.m16n8k8.row.col.f32.tf32.tf32.f32 "
        "{%0,%1,%2,%3}, {%4,%5,%6,%7}, {%8,%9}, {%0,%1,%2,%3};"
        : "+f"(c[0]), "+f"(c[1]), "+f"(c[2]), "+f"(c[3])
        : "r"(a[0]), "r"(a[1]), "r"(a[2]), "r"(a[3]),
          "r"(b[0]), "r"(b[1]));
}

// ---------------------------------------------------------------------------

__global__ void __launch_bounds__(THREADS, 2)
fused_gemm_tf32_kernel(const float* __restrict__ inp,
                       const float* __restrict__ w,
                       const float* __restrict__ bias,
                       float* __restrict__ out) {
    extern __shared__ char smem[];

    const int tid  = threadIdx.x;
    const int warp = tid >> 5;
    const int lane = tid & 31;
    const int gid  = lane >> 2;      // groupID (0..7)
    const int tig  = lane & 3;       // thread-in-group (0..3)
    const int wr   = warp >> 2;      // warp row (0..1) -> 64-row block
    const int wc   = warp & 3;       // warp col (0..3) -> 32-col block

    const int tn = blockIdx.x;       // D_OUT tile (0..3) — fastest: input L2 reuse
    const int tm = blockIdx.y;       // B tile (0..31)
    const int mm = blockIdx.z;       // matrix index (0..7)

    const float* Ag = inp + ((size_t)mm * BDIM + (size_t)tm * BM) * DIN;
    const float* Bg = w   + (size_t)mm * DIN * DOUT + (size_t)tn * BN;

    float acc[4][4][4];
#pragma unroll
    for (int mt = 0; mt < 4; ++mt)
#pragma unroll
        for (int nt = 0; nt < 4; ++nt)
#pragma unroll
            for (int i = 0; i < 4; ++i) acc[mt][nt][i] = 0.0f;

    // ---- async chunk loader: A 128x32 (row-major), B 32x128 (k-major, o contig)
    auto issue_chunk = [&](int c, int s) {
        char* sAc = smem + s * STAGE_BYTES;
        char* sBc = sAc + A_BYTES;
#pragma unroll
        for (int it = 0; it < 4; ++it) {
            int idx = tid + it * THREADS;      // 0..1023
            int row = idx >> 3;                // 0..127
            int q   = idx & 7;                 // 16B chunk within 32 floats
            const float* src = Ag + (size_t)row * DIN + c * KC + q * 4;
            cp16(smem_u32(sAc + row * (ASTR * 4) + q * 16), src);
        }
#pragma unroll
        for (int it = 0; it < 4; ++it) {
            int idx = tid + it * THREADS;      // 0..1023
            int k = idx >> 5;                  // 0..31
            int q = idx & 31;                  // 16B chunk within 128 floats
            const float* src = Bg + (size_t)(c * KC + k) * DOUT + q * 4;
            cp16(smem_u32(sBc + k * (BSTR * 4) + q * 16), src);
        }
        asm volatile("cp.async.commit_group;" ::: "memory");
    };

    // ---- compute one K-chunk (4 ksteps of 8) from stage s
    auto compute_chunk = [&](int s) {
        const float* sA = (const float*)(smem + s * STAGE_BYTES);
        const float* sB = (const float*)(smem + s * STAGE_BYTES + A_BYTES);
#pragma unroll
        for (int kk = 0; kk < 4; ++kk) {
            const int k0 = kk * 8;
            uint32_t af[4][4], bf[4][2];
#pragma unroll
            for (int mt = 0; mt < 4; ++mt) {
                const int r0 = wr * 64 + mt * 16 + gid;
                af[mt][0] = to_tf32(sA[(size_t)r0 * ASTR + k0 + tig]);
                af[mt][1] = to_tf32(sA[(size_t)(r0 + 8) * ASTR + k0 + tig]);
                af[mt][2] = to_tf32(sA[(size_t)r0 * ASTR + k0 + tig + 4]);
                af[mt][3] = to_tf32(sA[(size_t)(r0 + 8) * ASTR + k0 + tig + 4]);
            }
#pragma unroll
            for (int nt = 0; nt < 4; ++nt) {
                const int n0 = wc * 32 + nt * 8 + gid;
                bf[nt][0] = to_tf32(sB[(size_t)(k0 + tig) * BSTR + n0]);
                bf[nt][1] = to_tf32(sB[(size_t)(k0 + tig + 4) * BSTR + n0]);
            }
#pragma unroll
            for (int mt = 0; mt < 4; ++mt)
#pragma unroll
                for (int nt = 0; nt < 4; ++nt)
                    mma_tf32(acc[mt][nt], af[mt], bf[nt]);
        }
    };

    // ---- prologue: fill the pipeline
#pragma unroll
    for (int s = 0; s < NSTAGE; ++s) issue_chunk(s, s);

    // ---- main loop
#pragma unroll 1
    for (int c = 0; c < NCHUNK; ++c) {
        const int s = c % NSTAGE;
        if (c < NCHUNK - 2)
            asm volatile("cp.async.wait_group 2;" ::: "memory");
        else if (c == NCHUNK - 2)
            asm volatile("cp.async.wait_group 1;" ::: "memory");
        else
            asm volatile("cp.async.wait_group 0;" ::: "memory");
        __syncthreads();

        compute_chunk(s);

        __syncthreads();
        if (c + NSTAGE < NCHUNK) issue_chunk(c + NSTAGE, s);
    }

    // ---- epilogue: bias + relu, float2 stores
    const float* brow = bias + (size_t)mm * DOUT + tn * BN + wc * 32;
    float2 bv[4];
#pragma unroll
    for (int nt = 0; nt < 4; ++nt)
        bv[nt] = *reinterpret_cast<const float2*>(brow + nt * 8 + tig * 2);

#pragma unroll
    for (int mt = 0; mt < 4; ++mt) {
        const int r0 = tm * BM + wr * 64 + mt * 16 + gid;
        float* o0 = out + ((size_t)mm * BDIM + r0) * DOUT + tn * BN + wc * 32;
        float* o1 = o0 + 8 * DOUT;
#pragma unroll
        for (int nt = 0; nt < 4; ++nt) {
            float2 v0, v1;
            v0.x = fmaxf(acc[mt][nt][0] + bv[nt].x, 0.0f);
            v0.y = fmaxf(acc[mt][nt][1] + bv[nt].y, 0.0f);
            v1.x = fmaxf(acc[mt][nt][2] + bv[nt].x, 0.0f);
            v1.y = fmaxf(acc[mt][nt][3] + bv[nt].y, 0.0f);
            *reinterpret_cast<float2*>(o0 + nt * 8 + tig * 2) = v0;
            *reinterpret_cast<float2*>(o1 + nt * 8 + tig * 2) = v1;
        }
    }
}

// ---------------------------------------------------------------------------

extern "C" void kernel_launch(void* const* d_in, const int* in_sizes, int n_in,
                              void* d_out, int out_size) {
    const float* inp  = (const float*)d_in[0];   // [8, 4096, 512]
    const float* w    = (const float*)d_in[1];   // [8, 512, 512]
    const float* bias = (const float*)d_in[2];   // [8, 512]
    float* out = (float*)d_out;                  // [8, 4096, 512]
    (void)in_sizes; (void)n_in; (void)out_size;

    cudaFuncSetAttribute(fused_gemm_tf32_kernel,
                         cudaFuncAttributeMaxDynamicSharedMemorySize, SMEM_TOTAL);
    dim3 grid(DOUT / BN, BDIM / BM, MDIM);   // (4, 32, 8) = 1024 CTAs
    fused_gemm_tf32_kernel<<<grid, THREADS, SMEM_TOTAL>>>(inp, w, bias, out);
}

// round 4
// speedup vs baseline: 1.4147x; 1.4147x over previous
#include <cuda_runtime.h>
#include <cuda_fp16.h>
#include <cstdint>

// ============================================================================
// out[m,b,o] = relu( sum_i inp[m,b,i] * w[m,i,o] + bias[m,o] )
// M=8, B=4096, D_IN=512, D_OUT=512, fp32.
//
// Strategy (compute_100 family-portable):
//   1) pre-convert inp -> fp16 (same layout), w -> fp16 transposed [m][o][i]
//   2) fp16 mma.sync.m16n8k16 GEMM with ldmatrix fragment loads,
//      CTA tile 128x128, 8 warps of 64x32, K-chunks of 32, 4-stage cp.async
//      pipeline with ONE __syncthreads per chunk, fused bias+relu epilogue.
// ============================================================================

static constexpr int MDIM = 8;
static constexpr int BDIM = 4096;
static constexpr int DIN  = 512;
static constexpr int DOUT = 512;

static constexpr int BM = 128;
static constexpr int BN = 128;
static constexpr int KC = 32;              // K per pipeline chunk
static constexpr int NCHUNK = DIN / KC;    // 16
static constexpr int NSTAGE = 4;
static constexpr int THREADS = 256;

// SMEM rows: 32 halves (64B data) padded to 80B -> ldmatrix bank-quad index
// (5*row) % 8 is a permutation over any 8 consecutive rows => conflict-free.
static constexpr int ROWB = 80;                       // bytes per smem row
static constexpr int A_REGION = BM * ROWB;            // 10240
static constexpr int B_REGION = BN * ROWB;            // 10240
static constexpr int STAGE_BYTES = A_REGION + B_REGION;   // 20480
static constexpr int SMEM_TOTAL  = NSTAGE * STAGE_BYTES;  // 81920

// fp16 scratch (static device globals; no runtime allocation)
__device__ __align__(16) __half g_Ah[(size_t)MDIM * BDIM * DIN];   // 32 MB
__device__ __align__(16) __half g_Bh[(size_t)MDIM * DOUT * DIN];   // 4 MB

// ---------------- small helpers ----------------

__device__ __forceinline__ uint32_t smem_u32(const void* p) {
    uint32_t a;
    asm("{ .reg .u64 t; cvta.to.shared.u64 t, %1; cvt.u32.u64 %0, t; }"
        : "=r"(a) : "l"(p));
    return a;
}

__device__ __forceinline__ void cp16(uint32_t dst, const void* src) {
    asm volatile("cp.async.cg.shared.global [%0], [%1], 16;"
                 :: "r"(dst), "l"(src) : "memory");
}

__device__ __forceinline__ void ldmx4(uint32_t* r, uint32_t addr) {
    asm volatile("ldmatrix.sync.aligned.m8n8.x4.shared.b16 {%0,%1,%2,%3}, [%4];"
                 : "=r"(r[0]), "=r"(r[1]), "=r"(r[2]), "=r"(r[3]) : "r"(addr));
}

__device__ __forceinline__ void mma_f16(float* c, const uint32_t* a,
                                        const uint32_t* b) {
    asm volatile(
        "mma.sync.aligned.m16n8k16.row.col.f32.f16.f16.f32 "
        "{%0,%1,%2,%3}, {%4,%5,%6,%7}, {%8,%9}, {%0,%1,%2,%3};"
        : "+f"(c[0]), "+f"(c[1]), "+f"(c[2]), "+f"(c[3])
        : "r"(a[0]), "r"(a[1]), "r"(a[2]), "r"(a[3]),
          "r"(b[0]), "r"(b[1]));
}

// ---------------- preprocessing kernels ----------------

// inp fp32 -> g_Ah fp16, same [m][b][i] layout. 4 floats / thread.
__global__ void __launch_bounds__(256) convert_a_kernel(const float4* __restrict__ in) {
    const size_t i = (size_t)blockIdx.x * 256 + threadIdx.x;
    float4 v = in[i];
    __half2 h0 = __floats2half2_rn(v.x, v.y);
    __half2 h1 = __floats2half2_rn(v.z, v.w);
    uint2 st;
    st.x = *reinterpret_cast<uint32_t*>(&h0);
    st.y = *reinterpret_cast<uint32_t*>(&h1);
    reinterpret_cast<uint2*>(g_Ah)[i] = st;
}

// w[m][i][o] fp32 -> g_Bh[m][o][i] fp16 (transpose + convert)
__global__ void __launch_bounds__(256) convert_w_kernel(const float* __restrict__ w) {
    __shared__ float tile[32][33];
    const int m  = blockIdx.z;
    const int o0 = blockIdx.x * 32;
    const int i0 = blockIdx.y * 32;
    const int tx = threadIdx.x;          // 0..31
    const int ty = threadIdx.y;          // 0..7
    const float* wm = w + (size_t)m * DIN * DOUT;
    __half* bm = g_Bh + (size_t)m * DOUT * DIN;
#pragma unroll
    for (int j = 0; j < 32; j += 8)
        tile[ty + j][tx] = wm[(size_t)(i0 + ty + j) * DOUT + o0 + tx];
    __syncthreads();
#pragma unroll
    for (int j = 0; j < 32; j += 8)
        bm[(size_t)(o0 + ty + j) * DIN + i0 + tx] = __float2half_rn(tile[tx][ty + j]);
}

// ---------------- main GEMM kernel ----------------

__global__ void __launch_bounds__(THREADS, 2)
fused_gemm_f16_kernel(const float* __restrict__ bias, float* __restrict__ out) {
    extern __shared__ char smem[];
    const uint32_t sbase = smem_u32(smem);

    const int tid  = threadIdx.x;
    const int warp = tid >> 5;
    const int lane = tid & 31;
    const int gid  = lane >> 2;      // groupID
    const int tig  = lane & 3;       // thread-in-group
    const int wr   = warp >> 2;      // warp row (0..1) -> 64 rows
    const int wc   = warp & 3;       // warp col (0..3) -> 32 cols

    const int tn = blockIdx.x;       // D_OUT tile (0..3) — fastest: A reuse in L2
    const int tm = blockIdx.y;       // B-dim tile (0..31)
    const int mm = blockIdx.z;       // matrix (0..7)

    const __half* Ag = g_Ah + ((size_t)mm * BDIM + (size_t)tm * BM) * DIN;
    const __half* Bg = g_Bh + ((size_t)mm * DOUT + (size_t)tn * BN) * DIN;

    float acc[4][4][4];
#pragma unroll
    for (int mt = 0; mt < 4; ++mt)
#pragma unroll
        for (int nt = 0; nt < 4; ++nt)
#pragma unroll
            for (int i = 0; i < 4; ++i) acc[mt][nt][i] = 0.0f;

    // ---- async loader for chunk c into stage s (one commit group)
    auto issue_chunk = [&](int c, int s) {
        const uint32_t sA = sbase + s * STAGE_BYTES;
        const uint32_t sB = sA + A_REGION;
#pragma unroll
        for (int it = 0; it < 2; ++it) {
            int idx = tid + it * THREADS;        // 0..511
            int row = idx >> 2;                  // 0..127
            int q   = idx & 3;                   // 16B quarter of 64B row
            cp16(sA + row * ROWB + q * 16, Ag + (size_t)row * DIN + c * KC + q * 8);
        }
#pragma unroll
        for (int it = 0; it < 2; ++it) {
            int idx = tid + it * THREADS;
            int n = idx >> 2;
            int q = idx & 3;
            cp16(sB + n * ROWB + q * 16, Bg + (size_t)n * DIN + c * KC + q * 8);
        }
        asm volatile("cp.async.commit_group;" ::: "memory");
    };

    // ---- ldmatrix base addresses (per-lane, stage-relative)
    // A x4: lanes 0-15 -> rows (l%16), col 0; lanes 16-31 -> rows, col +16B
    const uint32_t a_lane_off =
        (uint32_t)((wr * 64 + (lane & 15)) * ROWB + (lane >> 4) * 16);
    // B x4 (two n8 tiles): n = wc*32 + (l%8) + (l/16)*8, colByte = ((l/8)&1)*16
    const uint32_t b_lane_off =
        (uint32_t)((wc * 32 + (lane & 7) + ((lane >> 4) << 3)) * ROWB +
                   ((lane >> 3) & 1) * 16);

    // ---- compute one K-chunk (2 x k16) from stage s
    auto compute_chunk = [&](int s) {
        const uint32_t sA = sbase + s * STAGE_BYTES;
        const uint32_t sB = sA + A_REGION;
#pragma unroll
        for (int ks = 0; ks < 2; ++ks) {
            uint32_t af[4][4], bf[2][4];
#pragma unroll
            for (int mt = 0; mt < 4; ++mt)
                ldmx4(af[mt], sA + a_lane_off + mt * (16 * ROWB) + ks * 32);
#pragma unroll
            for (int p = 0; p < 2; ++p)
                ldmx4(bf[p], sB + b_lane_off + p * (16 * ROWB) + ks * 32);
#pragma unroll
            for (int mt = 0; mt < 4; ++mt) {
#pragma unroll
                for (int nt = 0; nt < 4; ++nt)
                    mma_f16(acc[mt][nt], af[mt], &bf[nt >> 1][(nt & 1) * 2]);
            }
        }
    };

    // ---- prologue: 3 chunks in flight
    issue_chunk(0, 0);
    issue_chunk(1, 1);
    issue_chunk(2, 2);

    // ---- main loop: ONE barrier per chunk
#pragma unroll 1
    for (int c = 0; c < NCHUNK; ++c) {
        if (c <= NCHUNK - 3)
            asm volatile("cp.async.wait_group 2;" ::: "memory");
        else if (c == NCHUNK - 2)
            asm volatile("cp.async.wait_group 1;" ::: "memory");
        else
            asm volatile("cp.async.wait_group 0;" ::: "memory");
        __syncthreads();   // chunk c visible to all; all warps done with chunk c-1

        if (c + 3 < NCHUNK)
            issue_chunk(c + 3, (c + 3) % NSTAGE);  // stage freed by chunk c-1

        compute_chunk(c % NSTAGE);
    }

    // ---- epilogue: bias + relu, float2 stores
    const float* brow = bias + (size_t)mm * DOUT + tn * BN + wc * 32;
    float2 bv[4];
#pragma unroll
    for (int nt = 0; nt < 4; ++nt)
        bv[nt] = *reinterpret_cast<const float2*>(brow + nt * 8 + tig * 2);

#pragma unroll
    for (int mt = 0; mt < 4; ++mt) {
        const int r0 = tm * BM + wr * 64 + mt * 16 + gid;
        float* o0 = out + ((size_t)mm * BDIM + r0) * DOUT + tn * BN + wc * 32;
        float* o1 = o0 + 8 * DOUT;
#pragma unroll
        for (int nt = 0; nt < 4; ++nt) {
            float2 v0, v1;
            v0.x = fmaxf(acc[mt][nt][0] + bv[nt].x, 0.0f);
            v0.y = fmaxf(acc[mt][nt][1] + bv[nt].y, 0.0f);
            v1.x = fmaxf(acc[mt][nt][2] + bv[nt].x, 0.0f);
            v1.y = fmaxf(acc[mt][nt][3] + bv[nt].y, 0.0f);
            *reinterpret_cast<float2*>(o0 + nt * 8 + tig * 2) = v0;
            *reinterpret_cast<float2*>(o1 + nt * 8 + tig * 2) = v1;
        }
    }
}

// ---------------------------------------------------------------------------

extern "C" void kernel_launch(void* const* d_in, const int* in_sizes, int n_in,
                              void* d_out, int out_size) {
    const float* inp  = (const float*)d_in[0];   // [8, 4096, 512]
    const float* w    = (const float*)d_in[1];   // [8, 512, 512]
    const float* bias = (const float*)d_in[2];   // [8, 512]
    float* out = (float*)d_out;                  // [8, 4096, 512]
    (void)in_sizes; (void)n_in; (void)out_size;

    // 1) fp32 -> fp16 conversions (A same layout; W transposed to [m][o][i])
    const size_t n4 = (size_t)MDIM * BDIM * DIN / 4;         // 4,194,304
    convert_a_kernel<<<(unsigned)(n4 / 256), 256>>>((const float4*)inp);
    convert_w_kernel<<<dim3(DOUT / 32, DIN / 32, MDIM), dim3(32, 8)>>>(w);

    // 2) fp16 tensor-core GEMM + bias + relu
    cudaFuncSetAttribute(fused_gemm_f16_kernel,
                         cudaFuncAttributeMaxDynamicSharedMemorySize, SMEM_TOTAL);
    dim3 grid(DOUT / BN, BDIM / BM, MDIM);   // (4, 32, 8) = 1024 CTAs
    fused_gemm_f16_kernel<<<grid, THREADS, SMEM_TOTAL>>>(bias, out);
}

// round 5
// speedup vs baseline: 1.6094x; 1.1376x over previous
#include <cuda_runtime.h>
#include <cuda_fp16.h>
#include <cstdint>

// ============================================================================
// out[m,b,o] = relu( sum_i inp[m,b,i] * w[m,i,o] + bias[m,o] )
// M=8, B=4096, D_IN=512, D_OUT=512, fp32.
//
// compute_100 path: fp16 mma.sync.m16n8k16 + ldmatrix.
// R5: KC=64 (8 chunks, 8 barriers), NSTAGE=3 (108KB smem, 2 CTAs/SM),
//     intra-chunk fragment double-buffering, MLP-4 convert_a.
// ============================================================================

static constexpr int MDIM = 8;
static constexpr int BDIM = 4096;
static constexpr int DIN  = 512;
static constexpr int DOUT = 512;

static constexpr int BM = 128;
static constexpr int BN = 128;
static constexpr int KC = 64;              // K per pipeline chunk
static constexpr int NCHUNK = DIN / KC;    // 8
static constexpr int NSTAGE = 3;
static constexpr int THREADS = 256;

// SMEM rows: 64 halves (128B data) padded to 144B. ldmatrix 16B-chunk bank-quad
// index (36r + 4q) % 32 is a permutation over any 8 consecutive rows ->
// conflict-free; 144 is 16B-aligned for cp.async.
static constexpr int ROWB = 144;
static constexpr int A_REGION = BM * ROWB;             // 18432
static constexpr int B_REGION = BN * ROWB;             // 18432
static constexpr int STAGE_BYTES = A_REGION + B_REGION;    // 36864
static constexpr int SMEM_TOTAL  = NSTAGE * STAGE_BYTES;   // 110592

// fp16 scratch (static device globals; no runtime allocation)
__device__ __align__(16) __half g_Ah[(size_t)MDIM * BDIM * DIN];   // 32 MB
__device__ __align__(16) __half g_Bh[(size_t)MDIM * DOUT * DIN];   // 4 MB

// ---------------- helpers ----------------

__device__ __forceinline__ uint32_t smem_u32(const void* p) {
    uint32_t a;
    asm("{ .reg .u64 t; cvta.to.shared.u64 t, %1; cvt.u32.u64 %0, t; }"
        : "=r"(a) : "l"(p));
    return a;
}

__device__ __forceinline__ void cp16(uint32_t dst, const void* src) {
    asm volatile("cp.async.cg.shared.global [%0], [%1], 16;"
                 :: "r"(dst), "l"(src) : "memory");
}

__device__ __forceinline__ void ldmx4(uint32_t* r, uint32_t addr) {
    asm volatile("ldmatrix.sync.aligned.m8n8.x4.shared.b16 {%0,%1,%2,%3}, [%4];"
                 : "=r"(r[0]), "=r"(r[1]), "=r"(r[2]), "=r"(r[3]) : "r"(addr));
}

__device__ __forceinline__ void mma_f16(float* c, const uint32_t* a,
                                        const uint32_t* b) {
    asm volatile(
        "mma.sync.aligned.m16n8k16.row.col.f32.f16.f16.f32 "
        "{%0,%1,%2,%3}, {%4,%5,%6,%7}, {%8,%9}, {%0,%1,%2,%3};"
        : "+f"(c[0]), "+f"(c[1]), "+f"(c[2]), "+f"(c[3])
        : "r"(a[0]), "r"(a[1]), "r"(a[2]), "r"(a[3]),
          "r"(b[0]), "r"(b[1]));
}

// ---------------- preprocessing ----------------

// inp fp32 -> g_Ah fp16 (same layout). MLP=4: 4 float4 loads in flight.
__global__ void __launch_bounds__(256) convert_a_kernel(const float4* __restrict__ in) {
    const size_t base = (size_t)blockIdx.x * 1024 + threadIdx.x;
    float4 v[4];
#pragma unroll
    for (int k = 0; k < 4; ++k) v[k] = in[base + k * 256];
#pragma unroll
    for (int k = 0; k < 4; ++k) {
        __half2 h0 = __floats2half2_rn(v[k].x, v[k].y);
        __half2 h1 = __floats2half2_rn(v[k].z, v[k].w);
        uint2 st;
        st.x = *reinterpret_cast<uint32_t*>(&h0);
        st.y = *reinterpret_cast<uint32_t*>(&h1);
        reinterpret_cast<uint2*>(g_Ah)[base + k * 256] = st;
    }
}

// w[m][i][o] fp32 -> g_Bh[m][o][i] fp16 (transpose + convert)
__global__ void __launch_bounds__(256) convert_w_kernel(const float* __restrict__ w) {
    __shared__ float tile[32][33];
    const int m  = blockIdx.z;
    const int o0 = blockIdx.x * 32;
    const int i0 = blockIdx.y * 32;
    const int tx = threadIdx.x;
    const int ty = threadIdx.y;
    const float* wm = w + (size_t)m * DIN * DOUT;
    __half* bm = g_Bh + (size_t)m * DOUT * DIN;
#pragma unroll
    for (int j = 0; j < 32; j += 8)
        tile[ty + j][tx] = wm[(size_t)(i0 + ty + j) * DOUT + o0 + tx];
    __syncthreads();
#pragma unroll
    for (int j = 0; j < 32; j += 8)
        bm[(size_t)(o0 + ty + j) * DIN + i0 + tx] = __float2half_rn(tile[tx][ty + j]);
}

// ---------------- main GEMM kernel ----------------

__global__ void __launch_bounds__(THREADS, 2)
fused_gemm_f16_kernel(const float* __restrict__ bias, float* __restrict__ out) {
    extern __shared__ char smem[];
    const uint32_t sbase = smem_u32(smem);

    const int tid  = threadIdx.x;
    const int warp = tid >> 5;
    const int lane = tid & 31;
    const int gid  = lane >> 2;
    const int tig  = lane & 3;
    const int wr   = warp >> 2;      // warp row (0..1) -> 64 rows
    const int wc   = warp & 3;       // warp col (0..3) -> 32 cols

    const int tn = blockIdx.x;       // D_OUT tile (0..3) — fastest: A reuse in L2
    const int tm = blockIdx.y;       // B-dim tile (0..31)
    const int mm = blockIdx.z;       // matrix (0..7)

    const __half* __restrict__ Ag = g_Ah + ((size_t)mm * BDIM + (size_t)tm * BM) * DIN;
    const __half* __restrict__ Bg = g_Bh + ((size_t)mm * DOUT + (size_t)tn * BN) * DIN;

    float acc[4][4][4];
#pragma unroll
    for (int mt = 0; mt < 4; ++mt)
#pragma unroll
        for (int nt = 0; nt < 4; ++nt)
#pragma unroll
            for (int i = 0; i < 4; ++i) acc[mt][nt][i] = 0.0f;

    // ---- async loader for chunk c into stage s: A 128x64h, B 128x64h
    auto issue_chunk = [&](int c, int s) {
        const uint32_t sA = sbase + s * STAGE_BYTES;
        const uint32_t sB = sA + A_REGION;
#pragma unroll
        for (int it = 0; it < 4; ++it) {
            int idx = tid + it * THREADS;        // 0..1023
            int row = idx >> 3;                  // 0..127
            int q   = idx & 7;                   // 16B eighth of 128B row
            cp16(sA + row * ROWB + q * 16, Ag + (size_t)row * DIN + c * KC + q * 8);
        }
#pragma unroll
        for (int it = 0; it < 4; ++it) {
            int idx = tid + it * THREADS;
            int n = idx >> 3;
            int q = idx & 7;
            cp16(sB + n * ROWB + q * 16, Bg + (size_t)n * DIN + c * KC + q * 8);
        }
        asm volatile("cp.async.commit_group;" ::: "memory");
    };

    // ---- per-lane ldmatrix base offsets (stage-relative)
    const uint32_t a_lane_off =
        (uint32_t)((wr * 64 + (lane & 15)) * ROWB + (lane >> 4) * 16);
    const uint32_t b_lane_off =
        (uint32_t)((wc * 32 + (lane & 7) + ((lane >> 4) << 3)) * ROWB +
                   ((lane >> 3) & 1) * 16);

    // ---- prologue: 2 chunks in flight
    issue_chunk(0, 0);
    issue_chunk(1, 1);

    // ---- main loop: one barrier per chunk, frag double-buffer inside
#pragma unroll 1
    for (int c = 0; c < NCHUNK; ++c) {
        if (c < NCHUNK - 1)
            asm volatile("cp.async.wait_group 1;" ::: "memory");
        else
            asm volatile("cp.async.wait_group 0;" ::: "memory");
        __syncthreads();   // chunk c visible; all warps done with chunk c-1

        const uint32_t sA = sbase + (c % NSTAGE) * STAGE_BYTES;
        const uint32_t sB = sA + A_REGION;

        uint32_t af[2][4][4], bf[2][2][4];

        // preload kstep 0
#pragma unroll
        for (int mt = 0; mt < 4; ++mt)
            ldmx4(af[0][mt], sA + a_lane_off + mt * (16 * ROWB));
#pragma unroll
        for (int p = 0; p < 2; ++p)
            ldmx4(bf[0][p], sB + b_lane_off + p * (16 * ROWB));

        // refill stage freed by chunk c-1 while we compute
        if (c + 2 < NCHUNK)
            issue_chunk(c + 2, (c + 2) % NSTAGE);

#pragma unroll
        for (int ks = 0; ks < 4; ++ks) {
            const int cur = ks & 1, nxt = cur ^ 1;
            if (ks < 3) {
                const uint32_t ko = (uint32_t)(ks + 1) * 32;   // 16 halves = 32B
#pragma unroll
                for (int mt = 0; mt < 4; ++mt)
                    ldmx4(af[nxt][mt], sA + a_lane_off + mt * (16 * ROWB) + ko);
#pragma unroll
                for (int p = 0; p < 2; ++p)
                    ldmx4(bf[nxt][p], sB + b_lane_off + p * (16 * ROWB) + ko);
            }
#pragma unroll
            for (int mt = 0; mt < 4; ++mt)
#pragma unroll
                for (int nt = 0; nt < 4; ++nt)
                    mma_f16(acc[mt][nt], af[cur][mt], &bf[cur][nt >> 1][(nt & 1) * 2]);
        }
    }

    // ---- epilogue: bias + relu, float2 stores
    const float* brow = bias + (size_t)mm * DOUT + tn * BN + wc * 32;
    float2 bv[4];
#pragma unroll
    for (int nt = 0; nt < 4; ++nt)
        bv[nt] = *reinterpret_cast<const float2*>(brow + nt * 8 + tig * 2);

#pragma unroll
    for (int mt = 0; mt < 4; ++mt) {
        const int r0 = tm * BM + wr * 64 + mt * 16 + gid;
        float* o0 = out + ((size_t)mm * BDIM + r0) * DOUT + tn * BN + wc * 32;
        float* o1 = o0 + 8 * DOUT;
#pragma unroll
        for (int nt = 0; nt < 4; ++nt) {
            float2 v0, v1;
            v0.x = fmaxf(acc[mt][nt][0] + bv[nt].x, 0.0f);
            v0.y = fmaxf(acc[mt][nt][1] + bv[nt].y, 0.0f);
            v1.x = fmaxf(acc[mt][nt][2] + bv[nt].x, 0.0f);
            v1.y = fmaxf(acc[mt][nt][3] + bv[nt].y, 0.0f);
            *reinterpret_cast<float2*>(o0 + nt * 8 + tig * 2) = v0;
            *reinterpret_cast<float2*>(o1 + nt * 8 + tig * 2) = v1;
        }
    }
}

// ---------------------------------------------------------------------------

extern "C" void kernel_launch(void* const* d_in, const int* in_sizes, int n_in,
                              void* d_out, int out_size) {
    const float* inp  = (const float*)d_in[0];   // [8, 4096, 512]
    const float* w    = (const float*)d_in[1];   // [8, 512, 512]
    const float* bias = (const float*)d_in[2];   // [8, 512]
    float* out = (float*)d_out;                  // [8, 4096, 512]
    (void)in_sizes; (void)n_in; (void)out_size;

    // 1) fp32 -> fp16 conversions
    const size_t n4 = (size_t)MDIM * BDIM * DIN / 4;     // 4,194,304 float4s
    convert_a_kernel<<<(unsigned)(n4 / 1024), 256>>>((const float4*)inp);
    convert_w_kernel<<<dim3(DOUT / 32, DIN / 32, MDIM), dim3(32, 8)>>>(w);

    // 2) fp16 tensor-core GEMM + bias + relu
    cudaFuncSetAttribute(fused_gemm_f16_kernel,
                         cudaFuncAttributeMaxDynamicSharedMemorySize, SMEM_TOTAL);
    dim3 grid(DOUT / BN, BDIM / BM, MDIM);   // (4, 32, 8) = 1024 CTAs
    fused_gemm_f16_kernel<<<grid, THREADS, SMEM_TOTAL>>>(bias, out);
}

// round 6
// speedup vs baseline: 1.6646x; 1.0343x over previous
#include <cuda_runtime.h>
#include <cuda_fp16.h>
#include <cstdint>

// ============================================================================
// out[m,b,o] = relu( sum_i inp[m,b,i] * w[m,i,o] + bias[m,o] )
// M=8, B=4096, D_IN=512, D_OUT=512, fp32.
//
// compute_100 path: fp16 mma.sync.m16n8k16 + ldmatrix.
// R6: 4 warps/CTA (2x2), warp tile 64x64 -> smem crossbar reads cut 33%,
//     KC=64, NSTAGE=3 (108KB smem, 2 CTAs/SM), frag double-buffering,
//     MLP-8 convert_a.
// ============================================================================

static constexpr int MDIM = 8;
static constexpr int BDIM = 4096;
static constexpr int DIN  = 512;
static constexpr int DOUT = 512;

static constexpr int BM = 128;
static constexpr int BN = 128;
static constexpr int KC = 64;              // K per pipeline chunk
static constexpr int NCHUNK = DIN / KC;    // 8
static constexpr int NSTAGE = 3;
static constexpr int THREADS = 128;        // 4 warps, 2x2 grid of 64x64 tiles

// SMEM rows: 64 halves (128B data) padded to 144B. ldmatrix phase (8 rows)
// hits banks 144r mod 128 = {0,16,...,112} -> conflict-free; 16B-aligned.
static constexpr int ROWB = 144;
static constexpr int A_REGION = BM * ROWB;             // 18432
static constexpr int B_REGION = BN * ROWB;             // 18432
static constexpr int STAGE_BYTES = A_REGION + B_REGION;    // 36864
static constexpr int SMEM_TOTAL  = NSTAGE * STAGE_BYTES;   // 110592

// fp16 scratch (static device globals; no runtime allocation)
__device__ __align__(16) __half g_Ah[(size_t)MDIM * BDIM * DIN];   // 32 MB
__device__ __align__(16) __half g_Bh[(size_t)MDIM * DOUT * DIN];   // 4 MB

// ---------------- helpers ----------------

__device__ __forceinline__ uint32_t smem_u32(const void* p) {
    uint32_t a;
    asm("{ .reg .u64 t; cvta.to.shared.u64 t, %1; cvt.u32.u64 %0, t; }"
        : "=r"(a) : "l"(p));
    return a;
}

__device__ __forceinline__ void cp16(uint32_t dst, const void* src) {
    asm volatile("cp.async.cg.shared.global [%0], [%1], 16;"
                 :: "r"(dst), "l"(src) : "memory");
}

__device__ __forceinline__ void ldmx4(uint32_t* r, uint32_t addr) {
    asm volatile("ldmatrix.sync.aligned.m8n8.x4.shared.b16 {%0,%1,%2,%3}, [%4];"
                 : "=r"(r[0]), "=r"(r[1]), "=r"(r[2]), "=r"(r[3]) : "r"(addr));
}

__device__ __forceinline__ void mma_f16(float* c, const uint32_t* a,
                                        const uint32_t* b) {
    asm volatile(
        "mma.sync.aligned.m16n8k16.row.col.f32.f16.f16.f32 "
        "{%0,%1,%2,%3}, {%4,%5,%6,%7}, {%8,%9}, {%0,%1,%2,%3};"
        : "+f"(c[0]), "+f"(c[1]), "+f"(c[2]), "+f"(c[3])
        : "r"(a[0]), "r"(a[1]), "r"(a[2]), "r"(a[3]),
          "r"(b[0]), "r"(b[1]));
}

// ---------------- preprocessing ----------------

// inp fp32 -> g_Ah fp16 (same layout). MLP=8.
__global__ void __launch_bounds__(256) convert_a_kernel(const float4* __restrict__ in) {
    const size_t base = (size_t)blockIdx.x * 2048 + threadIdx.x;
    float4 v[8];
#pragma unroll
    for (int k = 0; k < 8; ++k) v[k] = in[base + k * 256];
#pragma unroll
    for (int k = 0; k < 8; ++k) {
        __half2 h0 = __floats2half2_rn(v[k].x, v[k].y);
        __half2 h1 = __floats2half2_rn(v[k].z, v[k].w);
        uint2 st;
        st.x = *reinterpret_cast<uint32_t*>(&h0);
        st.y = *reinterpret_cast<uint32_t*>(&h1);
        reinterpret_cast<uint2*>(g_Ah)[base + k * 256] = st;
    }
}

// w[m][i][o] fp32 -> g_Bh[m][o][i] fp16 (transpose + convert)
__global__ void __launch_bounds__(256) convert_w_kernel(const float* __restrict__ w) {
    __shared__ float tile[32][33];
    const int m  = blockIdx.z;
    const int o0 = blockIdx.x * 32;
    const int i0 = blockIdx.y * 32;
    const int tx = threadIdx.x;
    const int ty = threadIdx.y;
    const float* wm = w + (size_t)m * DIN * DOUT;
    __half* bm = g_Bh + (size_t)m * DOUT * DIN;
#pragma unroll
    for (int j = 0; j < 32; j += 8)
        tile[ty + j][tx] = wm[(size_t)(i0 + ty + j) * DOUT + o0 + tx];
    __syncthreads();
#pragma unroll
    for (int j = 0; j < 32; j += 8)
        bm[(size_t)(o0 + ty + j) * DIN + i0 + tx] = __float2half_rn(tile[tx][ty + j]);
}

// ---------------- main GEMM kernel ----------------

__global__ void __launch_bounds__(THREADS, 2)
fused_gemm_f16_kernel(const float* __restrict__ bias, float* __restrict__ out) {
    extern __shared__ char smem[];
    const uint32_t sbase = smem_u32(smem);

    const int tid  = threadIdx.x;
    const int warp = tid >> 5;
    const int lane = tid & 31;
    const int gid  = lane >> 2;
    const int tig  = lane & 3;
    const int wr   = warp >> 1;      // warp row (0..1) -> 64 rows
    const int wc   = warp & 1;       // warp col (0..1) -> 64 cols

    const int tn = blockIdx.x;       // D_OUT tile (0..3) — fastest: A reuse in L2
    const int tm = blockIdx.y;       // B-dim tile (0..31)
    const int mm = blockIdx.z;       // matrix (0..7)

    const __half* __restrict__ Ag = g_Ah + ((size_t)mm * BDIM + (size_t)tm * BM) * DIN;
    const __half* __restrict__ Bg = g_Bh + ((size_t)mm * DOUT + (size_t)tn * BN) * DIN;

    float acc[4][8][4];
#pragma unroll
    for (int mt = 0; mt < 4; ++mt)
#pragma unroll
        for (int nt = 0; nt < 8; ++nt)
#pragma unroll
            for (int i = 0; i < 4; ++i) acc[mt][nt][i] = 0.0f;

    // ---- async loader for chunk c into stage s: A 128x64h, B 128x64h
    auto issue_chunk = [&](int c, int s) {
        const uint32_t sA = sbase + s * STAGE_BYTES;
        const uint32_t sB = sA + A_REGION;
#pragma unroll
        for (int it = 0; it < 8; ++it) {
            int idx = tid + it * THREADS;        // 0..1023
            int row = idx >> 3;                  // 0..127
            int q   = idx & 7;                   // 16B eighth of 128B row
            cp16(sA + row * ROWB + q * 16, Ag + (size_t)row * DIN + c * KC + q * 8);
        }
#pragma unroll
        for (int it = 0; it < 8; ++it) {
            int idx = tid + it * THREADS;
            int n = idx >> 3;
            int q = idx & 7;
            cp16(sB + n * ROWB + q * 16, Bg + (size_t)n * DIN + c * KC + q * 8);
        }
        asm volatile("cp.async.commit_group;" ::: "memory");
    };

    // ---- per-lane ldmatrix base offsets (stage-relative)
    // A x4 tile mt: rows wr*64 + mt*16 + (l&15), colByte (l>>4)*16
    const uint32_t a_lane_off =
        (uint32_t)((wr * 64 + (lane & 15)) * ROWB + (lane >> 4) * 16);
    // B x4 pair p (covers n8-tiles 2p, 2p+1): rows wc*64 + p*16 + (l&7) + ((l>>4)<<3)
    const uint32_t b_lane_off =
        (uint32_t)((wc * 64 + (lane & 7) + ((lane >> 4) << 3)) * ROWB +
                   ((lane >> 3) & 1) * 16);

    // ---- prologue: 2 chunks in flight
    issue_chunk(0, 0);
    issue_chunk(1, 1);

    // ---- main loop: one barrier per chunk, frag double-buffer inside
#pragma unroll 1
    for (int c = 0; c < NCHUNK; ++c) {
        if (c < NCHUNK - 1)
            asm volatile("cp.async.wait_group 1;" ::: "memory");
        else
            asm volatile("cp.async.wait_group 0;" ::: "memory");
        __syncthreads();   // chunk c visible; all warps done with chunk c-1

        const uint32_t sA = sbase + (c % NSTAGE) * STAGE_BYTES;
        const uint32_t sB = sA + A_REGION;

        uint32_t af[2][4][4], bf[2][4][4];

        // preload kstep 0
#pragma unroll
        for (int mt = 0; mt < 4; ++mt)
            ldmx4(af[0][mt], sA + a_lane_off + mt * (16 * ROWB));
#pragma unroll
        for (int p = 0; p < 4; ++p)
            ldmx4(bf[0][p], sB + b_lane_off + p * (16 * ROWB));

        // refill stage freed by chunk c-1 while we compute
        if (c + 2 < NCHUNK)
            issue_chunk(c + 2, (c + 2) % NSTAGE);

#pragma unroll
        for (int ks = 0; ks < 4; ++ks) {
            const int cur = ks & 1, nxt = cur ^ 1;
            if (ks < 3) {
                const uint32_t ko = (uint32_t)(ks + 1) * 32;   // 16 halves = 32B
#pragma unroll
                for (int mt = 0; mt < 4; ++mt)
                    ldmx4(af[nxt][mt], sA + a_lane_off + mt * (16 * ROWB) + ko);
#pragma unroll
                for (int p = 0; p < 4; ++p)
                    ldmx4(bf[nxt][p], sB + b_lane_off + p * (16 * ROWB) + ko);
            }
#pragma unroll
            for (int mt = 0; mt < 4; ++mt)
#pragma unroll
                for (int nt = 0; nt < 8; ++nt)
                    mma_f16(acc[mt][nt], af[cur][mt], &bf[cur][nt >> 1][(nt & 1) * 2]);
        }
    }

    // ---- epilogue: bias + relu, float2 stores
    const float* brow = bias + (size_t)mm * DOUT + tn * BN + wc * 64;
    float2 bv[8];
#pragma unroll
    for (int nt = 0; nt < 8; ++nt)
        bv[nt] = *reinterpret_cast<const float2*>(brow + nt * 8 + tig * 2);

#pragma unroll
    for (int mt = 0; mt < 4; ++mt) {
        const int r0 = tm * BM + wr * 64 + mt * 16 + gid;
        float* o0 = out + ((size_t)mm * BDIM + r0) * DOUT + tn * BN + wc * 64;
        float* o1 = o0 + 8 * DOUT;
#pragma unroll
        for (int nt = 0; nt < 8; ++nt) {
            float2 v0, v1;
            v0.x = fmaxf(acc[mt][nt][0] + bv[nt].x, 0.0f);
            v0.y = fmaxf(acc[mt][nt][1] + bv[nt].y, 0.0f);
            v1.x = fmaxf(acc[mt][nt][2] + bv[nt].x, 0.0f);
            v1.y = fmaxf(acc[mt][nt][3] + bv[nt].y, 0.0f);
            *reinterpret_cast<float2*>(o0 + nt * 8 + tig * 2) = v0;
            *reinterpret_cast<float2*>(o1 + nt * 8 + tig * 2) = v1;
        }
    }
}

// ---------------------------------------------------------------------------

extern "C" void kernel_launch(void* const* d_in, const int* in_sizes, int n_in,
                              void* d_out, int out_size) {
    const float* inp  = (const float*)d_in[0];   // [8, 4096, 512]
    const float* w    = (const float*)d_in[1];   // [8, 512, 512]
    const float* bias = (const float*)d_in[2];   // [8, 512]
    float* out = (float*)d_out;                  // [8, 4096, 512]
    (void)in_sizes; (void)n_in; (void)out_size;

    // 1) fp32 -> fp16 conversions
    const size_t n4 = (size_t)MDIM * BDIM * DIN / 4;     // 4,194,304 float4s
    convert_a_kernel<<<(unsigned)(n4 / 2048), 256>>>((const float4*)inp);
    convert_w_kernel<<<dim3(DOUT / 32, DIN / 32, MDIM), dim3(32, 8)>>>(w);

    // 2) fp16 tensor-core GEMM + bias + relu
    cudaFuncSetAttribute(fused_gemm_f16_kernel,
                         cudaFuncAttributeMaxDynamicSharedMemorySize, SMEM_TOTAL);
    dim3 grid(DOUT / BN, BDIM / BM, MDIM);   // (4, 32, 8) = 1024 CTAs
    fused_gemm_f16_kernel<<<grid, THREADS, SMEM_TOTAL>>>(bias, out);
}